// round 13
// baseline (speedup 1.0000x reference)
#include <cuda_runtime.h>
#include <cuda_fp16.h>

#define NUM_NODES 100000
#define EMB_DIM   64
#define NUM_EDGES 1280000
#define CAP       64        // per-node bucket capacity (P(overflow) ~ 3e-18)
#define CAP_SHIFT 6
#define NPB       32        // nodes per pull block (256 threads / 8 lanes)

// ---- scratch (static device globals; no allocation allowed) ----
// Propagated states stored as y = dinv * x, fp16: 8 uint4 (32 uints) per node row.
__device__ __align__(16) unsigned g_E[NUM_NODES * 32];  // y0 = dinv*emb
__device__ __align__(16) unsigned g_A[NUM_NODES * 32];  // y1
__device__ __align__(16) unsigned g_B[NUM_NODES * 32];  // y2
__device__ float g_dinv[NUM_NODES];      // deg^-1/2 (0 if deg==0)
__device__ float g_sqd[NUM_NODES];       // deg^+1/2 (0 if deg==0)
__device__ int   g_deg[NUM_NODES];       // zero at load; self-cleaned by prep
__device__ int   g_degc[NUM_NODES];      // stable copy for the pull kernels
__device__ int   g_csp[NUM_NODES * CAP]; // padded CSR: src per slot

// Single-pass CSR build: rank from the atomic, direct store into the padded
// bucket. 4 edges/thread so the 4 ATOMG returns overlap (MLP=4 vs 318 cyc).
__global__ void build_kernel(const int* __restrict__ src, const int* __restrict__ dst) {
    int base = (blockIdx.x * blockDim.x + threadIdx.x) * 4;
    if (base + 4 <= NUM_EDGES) {
        int d0 = __ldg(&dst[base]),     d1 = __ldg(&dst[base + 1]);
        int d2 = __ldg(&dst[base + 2]), d3 = __ldg(&dst[base + 3]);
        int s0 = __ldg(&src[base]),     s1 = __ldg(&src[base + 1]);
        int s2 = __ldg(&src[base + 2]), s3 = __ldg(&src[base + 3]);
        int r0 = atomicAdd(&g_deg[d0], 1);
        int r1 = atomicAdd(&g_deg[d1], 1);
        int r2 = atomicAdd(&g_deg[d2], 1);
        int r3 = atomicAdd(&g_deg[d3], 1);
        g_csp[(d0 << CAP_SHIFT) + r0] = s0;
        g_csp[(d1 << CAP_SHIFT) + r1] = s1;
        g_csp[(d2 << CAP_SHIFT) + r2] = s2;
        g_csp[(d3 << CAP_SHIFT) + r3] = s3;
    } else {
        for (int e = base; e < NUM_EDGES; e++) {
            int d = dst[e];
            int r = atomicAdd(&g_deg[d], 1);
            g_csp[(d << CAP_SHIFT) + r] = src[e];
        }
    }
}

// Prep: per-node scalars (dinv, sqd, deg copy), self-clean g_deg, and convert
// this block's 256 emb rows to fp16 y-space (coalesced float4 sweep).
__global__ void prep_kernel(const float4* __restrict__ emb4) {
    __shared__ float sdinv[256];
    int i = blockIdx.x * 256 + threadIdx.x;
    int v = 0;
    if (i < NUM_NODES) {
        v = g_deg[i];
        g_deg[i] = 0;                      // clean for next invocation
    }
    float dv = (v > 0) ? rsqrtf((float)v) : 0.0f;
    if (i < NUM_NODES) {
        g_dinv[i] = dv;
        g_sqd[i]  = (v > 0) ? sqrtf((float)v) : 0.0f;
        g_degc[i] = v;
    }
    sdinv[threadIdx.x] = dv;
    __syncthreads();

    int nbase = blockIdx.x * 256;
    int fbase = nbase * 16;
    #pragma unroll
    for (int k = 0; k < 16; k++) {
        int idx  = k * 256 + threadIdx.x;
        int node = nbase + (idx >> 4);
        if (node < NUM_NODES) {
            float d = sdinv[idx >> 4];
            float4 val = __ldg(&emb4[fbase + idx]);
            __half2 lo = __floats2half2_rn(val.x * d, val.y * d);
            __half2 hi = __floats2half2_rn(val.z * d, val.w * d);
            uint2 p;
            p.x = *reinterpret_cast<unsigned*>(&lo);
            p.y = *reinterpret_cast<unsigned*>(&hi);
            reinterpret_cast<uint2*>(g_E)[fbase + idx] = p;
        }
    }
}

__device__ __forceinline__ float2 h2f(unsigned u) {
    __half2 h = *reinterpret_cast<__half2*>(&u);
    return __half22float2(h);
}

__device__ __forceinline__ unsigned uadd2(unsigned a, unsigned b) {
    __half2 r = __hadd2(*reinterpret_cast<__half2*>(&a),
                        *reinterpret_cast<__half2*>(&b));
    return *reinterpret_cast<unsigned*>(&r);
}

// Pull in y-space: sum = Σ_{s∈N(g)} y_in[s], bucket at [g*CAP, g*CAP+deg).
// 8 threads per dst node, one uint4 (8 halves) each.
// Phase A: prefetch ALL bucket indices into smem (coop, predicated by deg).
// Phase B: chunks of 8 independent gathers, indices from LDS (no global dep),
//          depth-3 fp16 tree reduce, fp32 accumulate.
// Grid covers nodes exactly (3125 * 32 == 100000), so no ragged-block guard.
//   layer 0: E -> A:  y1 = sum / deg
//   layer 1: A -> B:  y2 = sum / deg
//   layer 2: out = (emb + sqrt(deg)*(y1+y2) + dinv*sum) * 0.25
__global__ void __launch_bounds__(256) pull_kernel(const float4* __restrict__ emb4,
                                                   float4* __restrict__ out4,
                                                   int layer) {
    __shared__ int s_idx[NPB * CAP];               // 8 KB
    int tid     = threadIdx.x;
    int local_n = tid >> 3;                        // node within block (0..31)
    int c       = tid & 7;                         // uint4 lane within node
    int g       = blockIdx.x * NPB + local_n;      // dst node (always < NUM_NODES)

    const uint4* xin;
    if (layer == 0)      xin = (const uint4*)g_E;
    else if (layer == 1) xin = (const uint4*)g_A;
    else                 xin = (const uint4*)g_B;

    int deg  = __ldg(&g_degc[g]);
    int gbeg = g << CAP_SHIFT;
    int sbase = local_n * CAP;

    // Phase A: cooperative index prefetch (8 lanes x 8 strided entries)
    #pragma unroll
    for (int k = 0; k < 8; k++) {
        int p = (k << 3) + c;
        if (p < deg) s_idx[sbase + p] = __ldg(&g_csp[gbeg + p]);
    }
    __syncwarp();   // index producers/consumers are the same 8-lane group (same warp)

    float acc[8] = {0.f, 0.f, 0.f, 0.f, 0.f, 0.f, 0.f, 0.f};

    for (int ebase = 0; ebase < deg; ebase += 8) {
        uint4 v[8];
        #pragma unroll
        for (int j = 0; j < 8; j++) {
            int e = ebase + j;
            uint4 vv = make_uint4(0u, 0u, 0u, 0u);
            if (e < deg) {
                int s = s_idx[sbase + e];          // LDS broadcast, 29 cyc
                vv = __ldg(&xin[s * 8 + c]);       // 8 independent gathers in flight
            }
            v[j] = vv;
        }
        // depth-3 fp16 tree, then one fp32 accumulate per component
        unsigned sx = uadd2(uadd2(uadd2(v[0].x, v[1].x), uadd2(v[2].x, v[3].x)),
                            uadd2(uadd2(v[4].x, v[5].x), uadd2(v[6].x, v[7].x)));
        unsigned sy = uadd2(uadd2(uadd2(v[0].y, v[1].y), uadd2(v[2].y, v[3].y)),
                            uadd2(uadd2(v[4].y, v[5].y), uadd2(v[6].y, v[7].y)));
        unsigned sz = uadd2(uadd2(uadd2(v[0].z, v[1].z), uadd2(v[2].z, v[3].z)),
                            uadd2(uadd2(v[4].z, v[5].z), uadd2(v[6].z, v[7].z)));
        unsigned sw = uadd2(uadd2(uadd2(v[0].w, v[1].w), uadd2(v[2].w, v[3].w)),
                            uadd2(uadd2(v[4].w, v[5].w), uadd2(v[6].w, v[7].w)));
        float2 f;
        f = h2f(sx); acc[0] += f.x; acc[1] += f.y;
        f = h2f(sy); acc[2] += f.x; acc[3] += f.y;
        f = h2f(sz); acc[4] += f.x; acc[5] += f.y;
        f = h2f(sw); acc[6] += f.x; acc[7] += f.y;
    }

    if (layer < 2) {
        float dv = __ldg(&g_dinv[g]);
        float inv_deg = dv * dv;            // 1/deg (0 if deg==0)
        __half2 h0 = __floats2half2_rn(acc[0] * inv_deg, acc[1] * inv_deg);
        __half2 h1 = __floats2half2_rn(acc[2] * inv_deg, acc[3] * inv_deg);
        __half2 h2 = __floats2half2_rn(acc[4] * inv_deg, acc[5] * inv_deg);
        __half2 h3 = __floats2half2_rn(acc[6] * inv_deg, acc[7] * inv_deg);
        uint4 p;
        p.x = *reinterpret_cast<unsigned*>(&h0);
        p.y = *reinterpret_cast<unsigned*>(&h1);
        p.z = *reinterpret_cast<unsigned*>(&h2);
        p.w = *reinterpret_cast<unsigned*>(&h3);
        uint4* xout = (layer == 0) ? (uint4*)g_A : (uint4*)g_B;
        xout[g * 8 + c] = p;
    } else {
        float dv = __ldg(&g_dinv[g]);
        float sq = __ldg(&g_sqd[g]);        // sqrt(deg)
        uint4 ap = ((const uint4*)g_A)[g * 8 + c];
        uint4 bp = ((const uint4*)g_B)[g * 8 + c];
        float2 a0 = h2f(ap.x), a1 = h2f(ap.y), a2 = h2f(ap.z), a3 = h2f(ap.w);
        float2 b0 = h2f(bp.x), b1 = h2f(bp.y), b2 = h2f(bp.z), b3 = h2f(bp.w);
        int base = g * 16 + c * 2;          // float4 index into emb/out
        float4 e0 = __ldg(&emb4[base]);
        float4 e1 = __ldg(&emb4[base + 1]);
        float4 r0, r1;
        r0.x = (e0.x + sq * (a0.x + b0.x) + dv * acc[0]) * 0.25f;
        r0.y = (e0.y + sq * (a0.y + b0.y) + dv * acc[1]) * 0.25f;
        r0.z = (e0.z + sq * (a1.x + b1.x) + dv * acc[2]) * 0.25f;
        r0.w = (e0.w + sq * (a1.y + b1.y) + dv * acc[3]) * 0.25f;
        r1.x = (e1.x + sq * (a2.x + b2.x) + dv * acc[4]) * 0.25f;
        r1.y = (e1.y + sq * (a2.y + b2.y) + dv * acc[5]) * 0.25f;
        r1.z = (e1.z + sq * (a3.x + b3.x) + dv * acc[6]) * 0.25f;
        r1.w = (e1.w + sq * (a3.y + b3.y) + dv * acc[7]) * 0.25f;
        out4[base]     = r0;
        out4[base + 1] = r1;
    }
}

extern "C" void kernel_launch(void* const* d_in, const int* in_sizes, int n_in,
                              void* d_out, int out_size) {
    const int*   edge = (const int*)d_in[0];   // [2, NUM_EDGES]
    const float* emb  = (const float*)d_in[1]; // [NUM_NODES, EMB_DIM]
    const int* src = edge;
    const int* dst = edge + NUM_EDGES;
    const float4* emb4 = (const float4*)emb;
    float4* out4 = (float4*)d_out;

    const int TPB = 256;

    // g_deg is zero at module load and re-zeroed by prep_kernel each run.
    build_kernel<<<(NUM_EDGES / 4 + TPB - 1) / TPB, TPB>>>(src, dst);
    prep_kernel<<<(NUM_NODES + 255) / 256, 256>>>(emb4);

    const int pull_blocks = NUM_NODES / NPB;   // 3125, exact
    pull_kernel<<<pull_blocks, TPB>>>(emb4, out4, 0);  // E -> A
    pull_kernel<<<pull_blocks, TPB>>>(emb4, out4, 1);  // A -> B
    pull_kernel<<<pull_blocks, TPB>>>(emb4, out4, 2);  // B -> out (fused)
}

// round 14
// speedup vs baseline: 1.0766x; 1.0766x over previous
#include <cuda_runtime.h>
#include <cuda_fp16.h>

#define NUM_NODES 100000
#define EMB_DIM   64
#define NUM_EDGES 1280000
#define CAP       64        // per-node bucket capacity (P(overflow) ~ 3e-18)
#define CAP_SHIFT 6

// ---- scratch (static device globals; no allocation allowed) ----
// Propagated states stored as y = dinv * x, fp16: 8 uint4 (32 uints) per node row.
__device__ __align__(16) unsigned g_E[NUM_NODES * 32];  // y0 = dinv*emb
__device__ __align__(16) unsigned g_A[NUM_NODES * 32];  // y1
__device__ __align__(16) unsigned g_B[NUM_NODES * 32];  // y2
__device__ float g_dinv[NUM_NODES];      // deg^-1/2 (0 if deg==0)
__device__ float g_sqd[NUM_NODES];       // deg^+1/2 (0 if deg==0)
__device__ int   g_deg[NUM_NODES];       // zero at load; self-cleaned by prep
__device__ int   g_degc[NUM_NODES];      // stable copy for the pull kernels
__device__ int   g_csp[NUM_NODES * CAP]; // padded CSR: src per slot

// Single-pass CSR build: rank from the atomic, direct store into the padded
// bucket. 4 edges/thread so the 4 ATOMG returns overlap (MLP=4 vs 318 cyc).
__global__ void build_kernel(const int* __restrict__ src, const int* __restrict__ dst) {
    int base = (blockIdx.x * blockDim.x + threadIdx.x) * 4;
    if (base + 4 <= NUM_EDGES) {
        int d0 = __ldg(&dst[base]),     d1 = __ldg(&dst[base + 1]);
        int d2 = __ldg(&dst[base + 2]), d3 = __ldg(&dst[base + 3]);
        int s0 = __ldg(&src[base]),     s1 = __ldg(&src[base + 1]);
        int s2 = __ldg(&src[base + 2]), s3 = __ldg(&src[base + 3]);
        int r0 = atomicAdd(&g_deg[d0], 1);
        int r1 = atomicAdd(&g_deg[d1], 1);
        int r2 = atomicAdd(&g_deg[d2], 1);
        int r3 = atomicAdd(&g_deg[d3], 1);
        g_csp[(d0 << CAP_SHIFT) + r0] = s0;
        g_csp[(d1 << CAP_SHIFT) + r1] = s1;
        g_csp[(d2 << CAP_SHIFT) + r2] = s2;
        g_csp[(d3 << CAP_SHIFT) + r3] = s3;
    } else {
        for (int e = base; e < NUM_EDGES; e++) {
            int d = dst[e];
            int r = atomicAdd(&g_deg[d], 1);
            g_csp[(d << CAP_SHIFT) + r] = src[e];
        }
    }
}

// Prep: per-node scalars (dinv, sqd, deg copy), self-clean g_deg, and convert
// this block's 256 emb rows to fp16 y-space (coalesced float4 sweep).
__global__ void prep_kernel(const float4* __restrict__ emb4) {
    __shared__ float sdinv[256];
    int i = blockIdx.x * 256 + threadIdx.x;
    int v = 0;
    if (i < NUM_NODES) {
        v = g_deg[i];
        g_deg[i] = 0;                      // clean for next invocation
    }
    float dv = (v > 0) ? rsqrtf((float)v) : 0.0f;
    if (i < NUM_NODES) {
        g_dinv[i] = dv;
        g_sqd[i]  = (v > 0) ? sqrtf((float)v) : 0.0f;
        g_degc[i] = v;
    }
    sdinv[threadIdx.x] = dv;
    __syncthreads();

    int nbase = blockIdx.x * 256;
    int fbase = nbase * 16;
    #pragma unroll
    for (int k = 0; k < 16; k++) {
        int idx  = k * 256 + threadIdx.x;
        int node = nbase + (idx >> 4);
        if (node < NUM_NODES) {
            float d = sdinv[idx >> 4];
            float4 val = __ldg(&emb4[fbase + idx]);
            __half2 lo = __floats2half2_rn(val.x * d, val.y * d);
            __half2 hi = __floats2half2_rn(val.z * d, val.w * d);
            uint2 p;
            p.x = *reinterpret_cast<unsigned*>(&lo);
            p.y = *reinterpret_cast<unsigned*>(&hi);
            reinterpret_cast<uint2*>(g_E)[fbase + idx] = p;
        }
    }
}

__device__ __forceinline__ float2 h2f(unsigned u) {
    __half2 h = *reinterpret_cast<__half2*>(&u);
    return __half22float2(h);
}

__device__ __forceinline__ unsigned uadd2(unsigned a, unsigned b) {
    __half2 r = __hadd2(*reinterpret_cast<__half2*>(&a),
                        *reinterpret_cast<__half2*>(&b));
    return *reinterpret_cast<unsigned*>(&r);
}

// Pull in y-space: sum = Σ_{s∈N(g)} y_in[s], bucket at [g*CAP, g*CAP+deg).
// 8 threads per dst node, one uint4 (8 halves) each — a warp's gather
// instruction covers 4 distinct 128B lines.
// Software-pipelined: the next chunk's 4 indices are loaded while the current
// chunk's 4 gathers are in flight, so index latency never exposes.
// 4 gathered rows tree-reduced in fp16 (depth 2, HADD2), one fp32 accumulate.
//   layer 0: E -> A:  y1 = sum / deg
//   layer 1: A -> B:  y2 = sum / deg
//   layer 2: out = (emb + sqrt(deg)*(y1+y2) + dinv*sum) * 0.25
__global__ void __launch_bounds__(256) pull_kernel(const float4* __restrict__ emb4,
                                                   float4* __restrict__ out4,
                                                   int layer) {
    int g = blockIdx.x * (blockDim.x >> 3) + (threadIdx.x >> 3);  // dst node
    int c = threadIdx.x & 7;                                      // uint4 lane
    if (g >= NUM_NODES) return;

    const uint4* xin;
    if (layer == 0)      xin = (const uint4*)g_E;
    else if (layer == 1) xin = (const uint4*)g_A;
    else                 xin = (const uint4*)g_B;

    int beg = g << CAP_SHIFT;
    int end = beg + __ldg(&g_degc[g]);

    float acc[8] = {0.f, 0.f, 0.f, 0.f, 0.f, 0.f, 0.f, 0.f};

    int e = beg;
    if (e + 4 <= end) {
        // pipeline prologue: first chunk's indices
        int i0 = __ldg(&g_csp[e]);
        int i1 = __ldg(&g_csp[e + 1]);
        int i2 = __ldg(&g_csp[e + 2]);
        int i3 = __ldg(&g_csp[e + 3]);
        e += 4;
        while (e + 4 <= end) {
            // prefetch next chunk's indices (independent of current gathers)
            int j0 = __ldg(&g_csp[e]);
            int j1 = __ldg(&g_csp[e + 1]);
            int j2 = __ldg(&g_csp[e + 2]);
            int j3 = __ldg(&g_csp[e + 3]);
            uint4 v0 = __ldg(&xin[i0 * 8 + c]);
            uint4 v1 = __ldg(&xin[i1 * 8 + c]);
            uint4 v2 = __ldg(&xin[i2 * 8 + c]);
            uint4 v3 = __ldg(&xin[i3 * 8 + c]);
            unsigned sx = uadd2(uadd2(v0.x, v1.x), uadd2(v2.x, v3.x));
            unsigned sy = uadd2(uadd2(v0.y, v1.y), uadd2(v2.y, v3.y));
            unsigned sz = uadd2(uadd2(v0.z, v1.z), uadd2(v2.z, v3.z));
            unsigned sw = uadd2(uadd2(v0.w, v1.w), uadd2(v2.w, v3.w));
            float2 f;
            f = h2f(sx); acc[0] += f.x; acc[1] += f.y;
            f = h2f(sy); acc[2] += f.x; acc[3] += f.y;
            f = h2f(sz); acc[4] += f.x; acc[5] += f.y;
            f = h2f(sw); acc[6] += f.x; acc[7] += f.y;
            i0 = j0; i1 = j1; i2 = j2; i3 = j3;
            e += 4;
        }
        // pipeline drain: last full chunk
        {
            uint4 v0 = __ldg(&xin[i0 * 8 + c]);
            uint4 v1 = __ldg(&xin[i1 * 8 + c]);
            uint4 v2 = __ldg(&xin[i2 * 8 + c]);
            uint4 v3 = __ldg(&xin[i3 * 8 + c]);
            unsigned sx = uadd2(uadd2(v0.x, v1.x), uadd2(v2.x, v3.x));
            unsigned sy = uadd2(uadd2(v0.y, v1.y), uadd2(v2.y, v3.y));
            unsigned sz = uadd2(uadd2(v0.z, v1.z), uadd2(v2.z, v3.z));
            unsigned sw = uadd2(uadd2(v0.w, v1.w), uadd2(v2.w, v3.w));
            float2 f;
            f = h2f(sx); acc[0] += f.x; acc[1] += f.y;
            f = h2f(sy); acc[2] += f.x; acc[3] += f.y;
            f = h2f(sz); acc[4] += f.x; acc[5] += f.y;
            f = h2f(sw); acc[6] += f.x; acc[7] += f.y;
        }
    }
    if (e + 2 <= end) {                      // 2-edge remainder: depth-1 tree
        int s0 = __ldg(&g_csp[e]);
        int s1 = __ldg(&g_csp[e + 1]);
        uint4 v0 = __ldg(&xin[s0 * 8 + c]);
        uint4 v1 = __ldg(&xin[s1 * 8 + c]);
        unsigned sx = uadd2(v0.x, v1.x);
        unsigned sy = uadd2(v0.y, v1.y);
        unsigned sz = uadd2(v0.z, v1.z);
        unsigned sw = uadd2(v0.w, v1.w);
        float2 f;
        f = h2f(sx); acc[0] += f.x; acc[1] += f.y;
        f = h2f(sy); acc[2] += f.x; acc[3] += f.y;
        f = h2f(sz); acc[4] += f.x; acc[5] += f.y;
        f = h2f(sw); acc[6] += f.x; acc[7] += f.y;
        e += 2;
    }
    if (e < end) {                           // 1-edge remainder
        int s0 = __ldg(&g_csp[e]);
        uint4 v0 = __ldg(&xin[s0 * 8 + c]);
        float2 f;
        f = h2f(v0.x); acc[0] += f.x; acc[1] += f.y;
        f = h2f(v0.y); acc[2] += f.x; acc[3] += f.y;
        f = h2f(v0.z); acc[4] += f.x; acc[5] += f.y;
        f = h2f(v0.w); acc[6] += f.x; acc[7] += f.y;
    }

    if (layer < 2) {
        float dv = __ldg(&g_dinv[g]);
        float inv_deg = dv * dv;            // 1/deg (0 if deg==0)
        __half2 h0 = __floats2half2_rn(acc[0] * inv_deg, acc[1] * inv_deg);
        __half2 h1 = __floats2half2_rn(acc[2] * inv_deg, acc[3] * inv_deg);
        __half2 h2 = __floats2half2_rn(acc[4] * inv_deg, acc[5] * inv_deg);
        __half2 h3 = __floats2half2_rn(acc[6] * inv_deg, acc[7] * inv_deg);
        uint4 p;
        p.x = *reinterpret_cast<unsigned*>(&h0);
        p.y = *reinterpret_cast<unsigned*>(&h1);
        p.z = *reinterpret_cast<unsigned*>(&h2);
        p.w = *reinterpret_cast<unsigned*>(&h3);
        uint4* xout = (layer == 0) ? (uint4*)g_A : (uint4*)g_B;
        xout[g * 8 + c] = p;
    } else {
        float dv = __ldg(&g_dinv[g]);
        float sq = __ldg(&g_sqd[g]);        // sqrt(deg)
        uint4 ap = ((const uint4*)g_A)[g * 8 + c];
        uint4 bp = ((const uint4*)g_B)[g * 8 + c];
        float2 a0 = h2f(ap.x), a1 = h2f(ap.y), a2 = h2f(ap.z), a3 = h2f(ap.w);
        float2 b0 = h2f(bp.x), b1 = h2f(bp.y), b2 = h2f(bp.z), b3 = h2f(bp.w);
        int base = g * 16 + c * 2;          // float4 index into emb/out
        float4 e0 = __ldg(&emb4[base]);
        float4 e1 = __ldg(&emb4[base + 1]);
        float4 r0, r1;
        r0.x = (e0.x + sq * (a0.x + b0.x) + dv * acc[0]) * 0.25f;
        r0.y = (e0.y + sq * (a0.y + b0.y) + dv * acc[1]) * 0.25f;
        r0.z = (e0.z + sq * (a1.x + b1.x) + dv * acc[2]) * 0.25f;
        r0.w = (e0.w + sq * (a1.y + b1.y) + dv * acc[3]) * 0.25f;
        r1.x = (e1.x + sq * (a2.x + b2.x) + dv * acc[4]) * 0.25f;
        r1.y = (e1.y + sq * (a2.y + b2.y) + dv * acc[5]) * 0.25f;
        r1.z = (e1.z + sq * (a3.x + b3.x) + dv * acc[6]) * 0.25f;
        r1.w = (e1.w + sq * (a3.y + b3.y) + dv * acc[7]) * 0.25f;
        out4[base]     = r0;
        out4[base + 1] = r1;
    }
}

extern "C" void kernel_launch(void* const* d_in, const int* in_sizes, int n_in,
                              void* d_out, int out_size) {
    const int*   edge = (const int*)d_in[0];   // [2, NUM_EDGES]
    const float* emb  = (const float*)d_in[1]; // [NUM_NODES, EMB_DIM]
    const int* src = edge;
    const int* dst = edge + NUM_EDGES;
    const float4* emb4 = (const float4*)emb;
    float4* out4 = (float4*)d_out;

    const int TPB = 256;

    // g_deg is zero at module load and re-zeroed by prep_kernel each run.
    build_kernel<<<(NUM_EDGES / 4 + TPB - 1) / TPB, TPB>>>(src, dst);
    prep_kernel<<<(NUM_NODES + 255) / 256, 256>>>(emb4);

    const int nodes_per_block = TPB / 8;   // 32 nodes per block
    const int pull_blocks = (NUM_NODES + nodes_per_block - 1) / nodes_per_block;

    pull_kernel<<<pull_blocks, TPB>>>(emb4, out4, 0);  // E -> A
    pull_kernel<<<pull_blocks, TPB>>>(emb4, out4, 1);  // A -> B
    pull_kernel<<<pull_blocks, TPB>>>(emb4, out4, 2);  // B -> out (fused)
}